// round 12
// baseline (speedup 1.0000x reference)
#include <cuda_runtime.h>
#include <math.h>
#include <stdint.h>

#define NS    2048
#define D     512
#define D4    128
#define DPAD  129          // padded float4 row stride in stage (kills bank conflicts)
#define LYR   8
#define NT    7            // layer pairs
#define NCLS  128
#define MAXN  64
#define MAXNP 65           // padded smem sim/mask row stride (kills 32-way conflicts)
#define SCAP  20           // staged rows: 20*129*16B = 41.3KB
#define KTOP  5
#define FULL  0xffffffffu

// ---------------- device scratch (no allocations allowed) ----------------
__device__ int           g_mem[NCLS * MAXN];     // full-class member lists
__device__ int           g_n[NCLS];
__device__ int           g_smap[NCLS * MAXN];    // subset member-position map
__device__ int           g_n2[NCLS];
__device__ float         g_sim[(size_t)LYR * NCLS * MAXN * MAXN];   // full-class sims
__device__ float         g_A[(size_t)LYR * NCLS * MAXN * MAXN];     // masked symmetric A
__device__ unsigned char g_msk[(size_t)LYR * NCLS * MAXN * MAXN];   // symmetric masks
__device__ float         g_ema[LYR * NCLS * MAXN];
__device__ float         g_pnum[NT * NCLS];
__device__ float         g_pden[NT * NCLS];
__device__ int           g_ctr = 0;

__device__ __forceinline__ void cp_async16(uint32_t smem_addr, const void* gptr) {
    asm volatile("cp.async.cg.shared.global [%0], [%1], 16;\n"
                 :: "r"(smem_addr), "l"(gptr) : "memory");
}

// ---------------- kernel 0: member lists ----------------
__global__ __launch_bounds__(256) void members_kernel(const int* __restrict__ labels,
                                                      const int* __restrict__ sids32) {
    __shared__ int scan[256];
    const int cls = blockIdx.x, tid = threadIdx.x;
    // sample_ids = arange. int64 -> int32 words [0,0,1,0,...]; word[2]==1 iff int64
    const int is64 = (sids32[2] == 1) ? 1 : 0;

    int loc[8]; int c = 0;
#pragma unroll
    for (int k = 0; k < 8; k++) {
        int gi = tid * 8 + k;
        int lb = is64 ? labels[2 * gi] : labels[gi];
        if (lb == cls) loc[c++] = gi;
    }
    scan[tid] = c;
    __syncthreads();
    for (int off = 1; off < 256; off <<= 1) {
        int v = (tid >= off) ? scan[tid - off] : 0;
        __syncthreads();
        scan[tid] += v;
        __syncthreads();
    }
    int start = scan[tid] - c;
    for (int k = 0; k < c; k++) {
        int pos = start + k;
        if (pos < MAXN) g_mem[cls * MAXN + pos] = loc[k];
    }
    if (tid == 255) g_n[cls] = scan[255] < MAXN ? scan[255] : MAXN;
}

// ---------------- kernel 1: per (layer,class) full-class cosine blocks -------------
// Warp handles i-row PAIR {2g, 2g+1} in registers; each j-row LDS read serves 2 dots.
__global__ __launch_bounds__(256, 4) void sims_kernel(const float* __restrict__ feats) {
    extern __shared__ float4 stage[];            // SCAP rows, DPAD float4 stride
    __shared__ int           midx[MAXN];
    __shared__ float         sinv[MAXN];
    __shared__ const float4* rowp[MAXN];

    const int cls = blockIdx.x & (NCLS - 1);
    const int l   = blockIdx.x >> 7;
    const int tid = threadIdx.x;
    const int n   = g_n[cls];
    if (n == 0) return;

    for (int r = tid; r < n; r += 256) midx[r] = g_mem[cls * MAXN + r];
    __syncthreads();

    const float* F = feats + (size_t)l * NS * D;
    const int nst = n < SCAP ? n : SCAP;
    {
        uint32_t sbase = (uint32_t)__cvta_generic_to_shared(stage);
        for (int q = tid; q < nst * D4; q += 256) {
            int r = q >> 7, cc = q & 127;
            cp_async16(sbase + (uint32_t)(r * DPAD + cc) * 16u,
                       (const float4*)(F + (size_t)midx[r] * D) + cc);
        }
        asm volatile("cp.async.commit_group;\ncp.async.wait_group 0;\n" ::: "memory");
    }
    for (int r = tid; r < n; r += 256)
        rowp[r] = (r < nst) ? (const float4*)(stage + r * DPAD)
                            : (const float4*)(F + (size_t)midx[r] * D);
    __syncthreads();

    const int w = tid >> 5, lane = tid & 31;

    // ---- inverse norms (warp per row; same reduction tree as before) ----
    for (int r = w; r < n; r += 8) {
        const float4* a = rowp[r];
        float ss = 0.f;
#pragma unroll
        for (int k = 0; k < 4; k++) {
            float4 v = a[lane + 32 * k];
            ss += v.x * v.x + v.y * v.y + v.z * v.z + v.w * v.w;
        }
#pragma unroll
        for (int o = 16; o; o >>= 1) ss += __shfl_xor_sync(FULL, ss, o);
        if (lane == 0) sinv[r] = 1.0f / fmaxf(sqrtf(ss), 1e-8f);
    }
    __syncthreads();

    // ---- sims: 2 i-rows per warp in registers; j-rows streamed from LDS once ----
    float* gsim = g_sim + (size_t)(l * NCLS + cls) * MAXN * MAXN;
    const int ngrp = (n + 1) >> 1;
    for (int g = w; g < ngrp; g += 8) {
        const int i0 = 2 * g, i1 = i0 + 1;
        const bool has1 = (i1 < n);
        float4 ar0[4], ar1[4];
        {
            const float4* a0 = rowp[i0];
#pragma unroll
            for (int k = 0; k < 4; k++) ar0[k] = a0[lane + 32 * k];
        }
        if (has1) {
            const float4* a1 = rowp[i1];
#pragma unroll
            for (int k = 0; k < 4; k++) ar1[k] = a1[lane + 32 * k];
        }
        const float s0 = sinv[i0];
        const float s1 = has1 ? sinv[i1] : 0.f;
        for (int j = 0; j < i0; j++) {
            const float4* b = rowp[j];
            float d0 = 0.f, d1 = 0.f;
#pragma unroll
            for (int k = 0; k < 4; k++) {
                float4 y = b[lane + 32 * k];
                d0 += ar0[k].x * y.x + ar0[k].y * y.y + ar0[k].z * y.z + ar0[k].w * y.w;
                if (has1)
                    d1 += ar1[k].x * y.x + ar1[k].y * y.y + ar1[k].z * y.z + ar1[k].w * y.w;
            }
#pragma unroll
            for (int o = 16; o; o >>= 1) {
                d0 += __shfl_xor_sync(FULL, d0, o);
                d1 += __shfl_xor_sync(FULL, d1, o);
            }
            if (lane == 0) {
                float sj = sinv[j];
                float v0 = fminf(fmaxf(d0 * s0 * sj, -1.0f), 1.0f);  // clip -> +/-1 in fp32
                gsim[i0 * MAXN + j] = v0;
                gsim[j * MAXN + i0] = v0;
                if (has1) {
                    float v1 = fminf(fmaxf(d1 * s1 * sj, -1.0f), 1.0f);
                    gsim[i1 * MAXN + j] = v1;
                    gsim[j * MAXN + i1] = v1;
                }
            }
        }
        if (has1) {   // pair (i1, i0) from registers only
            float d = 0.f;
#pragma unroll
            for (int k = 0; k < 4; k++)
                d += ar1[k].x * ar0[k].x + ar1[k].y * ar0[k].y
                   + ar1[k].z * ar0[k].z + ar1[k].w * ar0[k].w;
#pragma unroll
            for (int o = 16; o; o >>= 1) d += __shfl_xor_sync(FULL, d, o);
            if (lane == 0) {
                float v = fminf(fmaxf(d * s1 * s0, -1.0f), 1.0f);
                gsim[i1 * MAXN + i0] = v;
                gsim[i0 * MAXN + i1] = v;
            }
        }
    }
    // diag = clip(~1, 1-1e-8) -> exactly 1.0f in fp32
    for (int i = tid; i < n; i += 256) gsim[i * MAXN + i] = 1.0f;
}

// ---------------- warp-parallel knn: ema/keep then top-5 marking ----------------
// lanes hold row elements (j = lane, lane+32). top-5 = 5 warp-argmax rounds;
// tie-break: higher value, then LOWER index (== jax.lax.top_k + strict-> scan).
__device__ __forceinline__ void knn_warp(const float* sim, int n2,
                                         unsigned char* msk, float* ema,
                                         unsigned char* keep) {
    const int tid = threadIdx.x, w = tid >> 5, lane = tid & 31;
    for (int i = w; i < n2; i += 8)
        for (int j = lane; j < MAXN; j += 32) msk[i * MAXNP + j] = 0;
    __syncthreads();
    for (int i = w; i < n2; i += 8) {
        const float* row = sim + i * MAXNP;
        float v0 = (lane < n2)      ? row[lane]      : 0.f;
        float v1 = (lane + 32 < n2) ? row[lane + 32] : 0.f;
        float rs = fmaxf(v0, 0.f) + fmaxf(v1, 0.f);
        int dg   = (v0 > 0.f) + (v1 > 0.f);
        int cand = ((v0 > 0.f) && lane != i) + ((v1 > 0.f) && (lane + 32) != i);
#pragma unroll
        for (int o = 16; o; o >>= 1) {
            rs   += __shfl_xor_sync(FULL, rs, o);
            dg   += __shfl_xor_sync(FULL, dg, o);
            cand += __shfl_xor_sync(FULL, cand, o);
        }
        if (lane == 0) {
            float degf = (float)(dg > 0 ? dg : 1);
            float sc   = 1.0f / (1.0f + expf(-rs / degf));
            ema[i]  = 0.45f + 0.1f * sc;          // MOM*0.5 + (1-MOM)*score
            keep[i] = (cand >= KTOP) ? 1 : 0;
        }
    }
    __syncthreads();
    for (int i = w; i < n2; i += 8) {
        if (!keep[i]) continue;
        const float* row = sim + i * MAXNP;
        float v0 = (lane < n2      && lane != i)        ? row[lane]      : 0.f;
        float v1 = (lane + 32 < n2 && (lane + 32) != i) ? row[lane + 32] : 0.f;
#pragma unroll
        for (int t = 0; t < KTOP; t++) {
            float bv; int bj;
            if (v1 > v0) { bv = v1; bj = lane + 32; } else { bv = v0; bj = lane; }
#pragma unroll
            for (int o = 16; o; o >>= 1) {
                float ov = __shfl_xor_sync(FULL, bv, o);
                int   oj = __shfl_xor_sync(FULL, bj, o);
                if (ov > bv || (ov == bv && oj < bj)) { bv = ov; bj = oj; }
            }
            if (bv > 0.f) {                        // only strictly-positive eligible
                if (lane == 0 && keep[bj]) msk[i * MAXNP + bj] = 1;
                if (bj == lane)           v0 = 0.f;   // mark used
                else if (bj == lane + 32) v1 = 0.f;
            }
        }
    }
    __syncthreads();
}

// compacted store: symmetric mask, masked A, ema
__device__ __forceinline__ void store_compact(const float* sim, int n2, int l, int cls,
                                              const unsigned char* msk, const float* ema) {
    const int tid = threadIdx.x, w = tid >> 5, lane = tid & 31;
    float*         gA = g_A   + (size_t)(l * NCLS + cls) * MAXN * MAXN;
    unsigned char* gm = g_msk + (size_t)(l * NCLS + cls) * MAXN * MAXN;
    for (int i = w; i < n2; i += 8)
        for (int j = lane; j < MAXN; j += 32) {
            unsigned char sym = 0; float av = 0.f;
            if (j < n2) {
                sym = (unsigned char)(msk[i * MAXNP + j] | msk[j * MAXNP + i]);
                av  = sym ? sim[i * MAXNP + j] : 0.f;   // A = sim * M
            }
            gm[i * MAXN + j] = sym;
            gA[i * MAXN + j] = av;
        }
    if (tid < n2) g_ema[(l * NCLS + cls) * MAXN + tid] = ema[tid];
}

// ---------------- kernel 2: subset selection + layer-7 compacted outputs -----------
__global__ __launch_bounds__(256) void subset_kernel() {
    __shared__ float         sim[MAXN * MAXNP];
    __shared__ float         sim2[MAXN * MAXNP];
    __shared__ unsigned char msk[MAXN * MAXNP];
    __shared__ float         ema[MAXN];
    __shared__ unsigned char keep[MAXN], insub[MAXN];
    __shared__ int           smap[MAXN];
    __shared__ int           sn2;

    const int cls = blockIdx.x, tid = threadIdx.x;
    const int w = tid >> 5, lane = tid & 31;
    const int n = g_n[cls];
    if (n == 0) { if (tid == 0) g_n2[cls] = 0; return; }

    const float* gsim = g_sim + (size_t)((LYR - 1) * NCLS + cls) * MAXN * MAXN;
    for (int i = w; i < n; i += 8)
        for (int j = lane; j < n; j += 32)
            sim[i * MAXNP + j] = gsim[i * MAXN + j];
    for (int r = tid; r < n; r += 256) insub[r] = 0;
    __syncthreads();

    // keep: per-row candidate count (warp per row)
    for (int i = w; i < n; i += 8) {
        const float* row = sim + i * MAXNP;
        float v0 = (lane < n)      ? row[lane]      : 0.f;
        float v1 = (lane + 32 < n) ? row[lane + 32] : 0.f;
        int cand = ((v0 > 0.f) && lane != i) + ((v1 > 0.f) && (lane + 32) != i);
#pragma unroll
        for (int o = 16; o; o >>= 1) cand += __shfl_xor_sync(FULL, cand, o);
        if (lane == 0) keep[i] = (cand >= KTOP) ? 1 : 0;
    }
    __syncthreads();
    // top5 -> insub marking (warp per row)
    for (int i = w; i < n; i += 8) {
        if (!keep[i]) continue;
        const float* row = sim + i * MAXNP;
        float v0 = (lane < n      && lane != i)        ? row[lane]      : 0.f;
        float v1 = (lane + 32 < n && (lane + 32) != i) ? row[lane + 32] : 0.f;
#pragma unroll
        for (int t = 0; t < KTOP; t++) {
            float bv; int bj;
            if (v1 > v0) { bv = v1; bj = lane + 32; } else { bv = v0; bj = lane; }
#pragma unroll
            for (int o = 16; o; o >>= 1) {
                float ov = __shfl_xor_sync(FULL, bv, o);
                int   oj = __shfl_xor_sync(FULL, bj, o);
                if (ov > bv || (ov == bv && oj < bj)) { bv = ov; bj = oj; }
            }
            if (bv > 0.f) {
                if (lane == 0 && keep[bj]) { insub[i] = 1; insub[bj] = 1; }  // benign race
                if (bj == lane)           v0 = 0.f;
                else if (bj == lane + 32) v1 = 0.f;
            }
        }
    }
    __syncthreads();
    if (tid == 0) {
        int m = 0;
        for (int i = 0; i < n; i++)
            if (insub[i]) { smap[m] = i; g_smap[cls * MAXN + m] = i; m++; }
        sn2 = m;
        g_n2[cls] = m;
    }
    __syncthreads();
    const int n2 = sn2;
    if (n2 == 0) return;

    for (int i = w; i < n2; i += 8)
        for (int j = lane; j < n2; j += 32)
            sim2[i * MAXNP + j] = sim[smap[i] * MAXNP + smap[j]];
    __syncthreads();
    knn_warp(sim2, n2, msk, ema, keep);
    store_compact(sim2, n2, LYR - 1, cls, msk, ema);
}

// ---------------- kernel 3: per (class, layer 0..6) subset knn ----------------
__global__ __launch_bounds__(256) void knn_kernel() {
    __shared__ int           smap[MAXN];
    __shared__ float         sim[MAXN * MAXNP];
    __shared__ unsigned char msk[MAXN * MAXNP];
    __shared__ float         ema[MAXN];
    __shared__ unsigned char keep[MAXN];

    const int cls = blockIdx.x & (NCLS - 1);
    const int l   = blockIdx.x >> 7;        // 0..6
    const int tid = threadIdx.x;
    const int w = tid >> 5, lane = tid & 31;
    const int n2  = g_n2[cls];
    if (n2 == 0) return;

    for (int r = tid; r < n2; r += 256) smap[r] = g_smap[cls * MAXN + r];
    __syncthreads();
    const float* gsim = g_sim + (size_t)(l * NCLS + cls) * MAXN * MAXN;
    for (int i = w; i < n2; i += 8)
        for (int j = lane; j < n2; j += 32)
            sim[i * MAXNP + j] = gsim[smap[i] * MAXN + smap[j]];
    __syncthreads();
    knn_warp(sim, n2, msk, ema, keep);
    store_compact(sim, n2, l, cls, msk, ema);
}

// ---------------- kernel 4: block per class, warp per layer-pair + fused combine ---
__global__ __launch_bounds__(256) void accum_final(float* __restrict__ out) {
    __shared__ float esh[NT][MAXN];
    __shared__ int   done;

    const int cls = blockIdx.x;              // 0..127
    const int tid = threadIdx.x;
    const int w = tid >> 5, lane = tid & 31;
    const int n2  = g_n2[cls];

    if (n2 > 1) {
        for (int q = tid; q < NT * MAXN; q += 256) {
            int l = q >> 6, r = q & 63;
            esh[l][r] = g_ema[(l * NCLS + cls) * MAXN + r];
        }
        __syncthreads();
        if (w < NT) {                        // warp w handles layer pair (w, w+1)
            const size_t bp = (size_t)(w * NCLS + cls) * MAXN * MAXN;
            const size_t bc = (size_t)((w + 1) * NCLS + cls) * MAXN * MAXN;
            float pnum = 0.f, pden = 0.f;
            for (int p = lane; p < n2 * MAXN; p += 32) {
                int ml = g_msk[bp + p];
                int mc = g_msk[bc + p];
                if (ml | mc) {
                    int i = p >> 6, j = p & 63;
                    float wt = esh[w][i] * esh[w][j];
                    float d  = g_A[bc + p] - g_A[bp + p];
                    pnum += d * d * wt;
                    pden += wt;
                }
            }
#pragma unroll
            for (int o = 16; o; o >>= 1) {
                pnum += __shfl_xor_sync(FULL, pnum, o);
                pden += __shfl_xor_sync(FULL, pden, o);
            }
            if (lane == 0) {
                g_pnum[w * NCLS + cls] = pnum;
                g_pden[w * NCLS + cls] = pden;
            }
        }
    } else if (tid < NT) {
        g_pnum[tid * NCLS + cls] = 0.f;
        g_pden[tid * NCLS + cls] = 0.f;
    }
    __threadfence();
    __syncthreads();
    if (tid == 0) {
        int old = atomicAdd(&g_ctr, 1);
        done = (old == NCLS - 1) ? 1 : 0;
    }
    __syncthreads();
    if (!done) return;

    // last block: deterministic combine of all 7*128 partials
    __shared__ float red[128];
    __shared__ float tnum[NT], tden[NT];
    for (int t2 = 0; t2 < NT; t2++) {
        if (tid < 128) red[tid] = g_pnum[t2 * NCLS + tid];
        __syncthreads();
        for (int s = 64; s; s >>= 1) { if (tid < s) red[tid] += red[tid + s]; __syncthreads(); }
        if (tid == 0) tnum[t2] = red[0];
        __syncthreads();
        if (tid < 128) red[tid] = g_pden[t2 * NCLS + tid];
        __syncthreads();
        for (int s = 64; s; s >>= 1) { if (tid < s) red[tid] += red[tid + s]; __syncthreads(); }
        if (tid == 0) tden[t2] = red[0];
        __syncthreads();
    }
    if (tid == 0) {
        float raw = 0.f;
        for (int t2 = 0; t2 < NT; t2++)
            if (tden[t2] > 0.f)                       // M_eff.sum() > 0 <=> any edge
                raw += tnum[t2] / fmaxf(tden[t2], 1e-8f);
        out[0] = 16.0f * (raw / 7.0f);                // LAMBDA_ALIGN_K * raw / (L-1)
        g_ctr = 0;                                    // reset for next graph replay
    }
}

extern "C" void kernel_launch(void* const* d_in, const int* in_sizes, int n_in,
                              void* d_out, int out_size) {
    const float* feats  = (const float*)d_in[0];
    const int*   labels = (const int*)d_in[1];   // int32 or int64; detected at runtime
    const int*   sids   = (const int*)d_in[2];
    float*       out    = (float*)d_out;

    const int DYN = SCAP * DPAD * 16;            // 41.3 KB padded stage
    cudaFuncSetAttribute(sims_kernel, cudaFuncAttributeMaxDynamicSharedMemorySize, DYN);

    members_kernel<<<NCLS, 256>>>(labels, sids);
    sims_kernel<<<LYR * NCLS, 256, DYN>>>(feats);
    subset_kernel<<<NCLS, 256>>>();
    knn_kernel<<<NT * NCLS, 256>>>();
    accum_final<<<NCLS, 256>>>(out);
}

// round 13
// speedup vs baseline: 1.1783x; 1.1783x over previous
#include <cuda_runtime.h>
#include <math.h>
#include <stdint.h>

#define NS    2048
#define D     512
#define D4    128
#define DPAD  129          // padded float4 row stride in stage (kills bank conflicts)
#define LYR   8
#define NT    7            // layer pairs
#define NCLS  128
#define MAXN  64
#define MAXNP 65           // padded smem sim/mask row stride (kills 32-way conflicts)
#define SCAP  20           // staged rows: 20*129*16B = 41.3KB
#define KTOP  5
#define FULL  0xffffffffu
#define BLK   (MAXN * MAXNP)

// ---------------- device scratch (no allocations allowed) ----------------
__device__ int   g_mem[NCLS * MAXN];     // full-class member lists
__device__ int   g_n[NCLS];
__device__ float g_sim[(size_t)LYR * NCLS * MAXN * MAXN];   // full-class sims
__device__ float g_pnum[NT * NCLS];
__device__ float g_pden[NT * NCLS];
__device__ int   g_ctr = 0;

__device__ __forceinline__ void cp_async16(uint32_t smem_addr, const void* gptr) {
    asm volatile("cp.async.cg.shared.global [%0], [%1], 16;\n"
                 :: "r"(smem_addr), "l"(gptr) : "memory");
}

// ---------------- kernel 0: member lists (unchanged from R11) ----------------
__global__ __launch_bounds__(256) void members_kernel(const int* __restrict__ labels,
                                                      const int* __restrict__ sids32) {
    __shared__ int scan[256];
    const int cls = blockIdx.x, tid = threadIdx.x;
    // sample_ids = arange. int64 -> int32 words [0,0,1,0,...]; word[2]==1 iff int64
    const int is64 = (sids32[2] == 1) ? 1 : 0;

    int loc[8]; int c = 0;
#pragma unroll
    for (int k = 0; k < 8; k++) {
        int gi = tid * 8 + k;
        int lb = is64 ? labels[2 * gi] : labels[gi];
        if (lb == cls) loc[c++] = gi;
    }
    scan[tid] = c;
    __syncthreads();
    for (int off = 1; off < 256; off <<= 1) {
        int v = (tid >= off) ? scan[tid - off] : 0;
        __syncthreads();
        scan[tid] += v;
        __syncthreads();
    }
    int start = scan[tid] - c;
    for (int k = 0; k < c; k++) {
        int pos = start + k;
        if (pos < MAXN) g_mem[cls * MAXN + pos] = loc[k];
    }
    if (tid == 255) g_n[cls] = scan[255] < MAXN ? scan[255] : MAXN;
}

// ---------------- kernel 1: per (layer,class) full-class sims (unchanged R11) ------
__global__ __launch_bounds__(256) void sims_kernel(const float* __restrict__ feats) {
    extern __shared__ float4 stage[];            // SCAP rows, DPAD float4 stride
    __shared__ int           midx[MAXN];
    __shared__ float         sinv[MAXN];
    __shared__ const float4* rowp[MAXN];

    const int cls = blockIdx.x & (NCLS - 1);
    const int l   = blockIdx.x >> 7;
    const int tid = threadIdx.x;
    const int n   = g_n[cls];
    if (n == 0) return;

    for (int r = tid; r < n; r += 256) midx[r] = g_mem[cls * MAXN + r];
    __syncthreads();

    const float* F = feats + (size_t)l * NS * D;
    const int nst = n < SCAP ? n : SCAP;
    {
        uint32_t sbase = (uint32_t)__cvta_generic_to_shared(stage);
        for (int q = tid; q < nst * D4; q += 256) {
            int r = q >> 7, cc = q & 127;
            cp_async16(sbase + (uint32_t)(r * DPAD + cc) * 16u,
                       (const float4*)(F + (size_t)midx[r] * D) + cc);
        }
        asm volatile("cp.async.commit_group;\ncp.async.wait_group 0;\n" ::: "memory");
    }
    for (int r = tid; r < n; r += 256)
        rowp[r] = (r < nst) ? (const float4*)(stage + r * DPAD)
                            : (const float4*)(F + (size_t)midx[r] * D);
    __syncthreads();

    const int w = tid >> 5, lane = tid & 31;

    for (int r = w; r < n; r += 8) {
        const float4* a = rowp[r];
        float ss = 0.f;
#pragma unroll
        for (int k = 0; k < 4; k++) {
            float4 v = a[lane + 32 * k];
            ss += v.x * v.x + v.y * v.y + v.z * v.z + v.w * v.w;
        }
#pragma unroll
        for (int o = 16; o; o >>= 1) ss += __shfl_xor_sync(FULL, ss, o);
        if (lane == 0) sinv[r] = 1.0f / fmaxf(sqrtf(ss), 1e-8f);
    }
    __syncthreads();

    float* gsim = g_sim + (size_t)(l * NCLS + cls) * MAXN * MAXN;
    for (int i = w; i < n; i += 8) {
        const float4* a = rowp[i];
        float4 ar[4];
#pragma unroll
        for (int k = 0; k < 4; k++) ar[k] = a[lane + 32 * k];
        const float si = sinv[i];
        for (int j = 0; j < i; j++) {
            const float4* b = rowp[j];
            float dot = 0.f;
#pragma unroll
            for (int k = 0; k < 4; k++) {
                float4 y = b[lane + 32 * k];
                dot += ar[k].x * y.x + ar[k].y * y.y + ar[k].z * y.z + ar[k].w * y.w;
            }
#pragma unroll
            for (int o = 16; o; o >>= 1) dot += __shfl_xor_sync(FULL, dot, o);
            if (lane == 0) {
                float s = dot * si * sinv[j];
                s = fminf(fmaxf(s, -1.0f), 1.0f);   // fp32 clip bounds round to +/-1
                gsim[i * MAXN + j] = s;
                gsim[j * MAXN + i] = s;
            }
        }
    }
    // diag = clip(~1, 1-1e-8) -> exactly 1.0f in fp32
    for (int i = tid; i < n; i += 256) gsim[i * MAXN + i] = 1.0f;
}

// top-5 with jax.lax.top_k tie-break (equal values -> lower index) — R11 verbatim
__device__ __forceinline__ void top5_row(const float* row, int n, int self, int* ch) {
#pragma unroll
    for (int t = 0; t < KTOP; t++) {
        float bv = 0.f;   // only strictly-positive sims are candidates
        int   bj = -1;
        for (int j = 0; j < n; j++) {
            if (j == self) continue;
            bool used = false;
            for (int u = 0; u < t; u++) if (ch[u] == j) used = true;
            if (used) continue;
            float v = row[j];
            if (v > bv) { bv = v; bj = j; }
        }
        ch[t] = bj;
    }
}

// ---------------- kernel 2: per-class mega (subset + 8 knn + 7 accum + combine) ----
// Dyn smem: lsim[8][64*65] f32 | l7[64*65] f32 | msk[8][64*65] u8  = 183,040 B
__global__ __launch_bounds__(256) void mega_kernel(float* __restrict__ out) {
    extern __shared__ char dsm[];
    float*         lsim = (float*)dsm;                       // 8 * BLK floats
    float*         l7   = lsim + LYR * BLK;                  // BLK floats
    unsigned char* msk  = (unsigned char*)(l7 + BLK);        // 8 * BLK bytes

    __shared__ float         ema[LYR][MAXN];
    __shared__ unsigned char keepL[LYR][MAXN];
    __shared__ unsigned char keepS[MAXN], insub[MAXN];
    __shared__ int           smap[MAXN];
    __shared__ int           sn2;
    __shared__ int           done;

    const int cls = blockIdx.x, tid = threadIdx.x;
    const int w = tid >> 5, lane = tid & 31;
    const int n = g_n[cls];
    int n2 = 0;

    if (n > 0) {
        // ---- phase 0: gather layer-7 full block, subset selection (R11 logic) ----
        const float* gsim7 = g_sim + (size_t)((LYR - 1) * NCLS + cls) * MAXN * MAXN;
        for (int i = w; i < n; i += 8)
            for (int j = lane; j < n; j += 32)
                l7[i * MAXNP + j] = gsim7[i * MAXN + j];
        for (int r = tid; r < n; r += 256) insub[r] = 0;
        __syncthreads();

        if (tid < n) {
            const float* row = l7 + tid * MAXNP;
            int cand = 0;
            for (int j = 0; j < n; j++)
                if (j != tid && row[j] > 0.f) cand++;
            keepS[tid] = (cand >= KTOP) ? 1 : 0;
        }
        __syncthreads();
        if (tid < n && keepS[tid]) {
            const float* row = l7 + tid * MAXNP;
            int ch[KTOP];
            top5_row(row, n, tid, ch);
#pragma unroll
            for (int t = 0; t < KTOP; t++) {
                int j = ch[t];
                if (j >= 0 && keepS[j]) { insub[tid] = 1; insub[j] = 1; }  // benign race
            }
        }
        __syncthreads();
        if (tid == 0) {
            int m = 0;
            for (int i = 0; i < n; i++)
                if (insub[i]) smap[m++] = i;
            sn2 = m;
        }
        __syncthreads();
        n2 = sn2;
    }

    if (n2 > 1) {
        // ---- phase 1: gather all 8 layers' subset sims; zero masks ----
        const int nn = n2 * n2;
        for (int q = tid; q < LYR * nn; q += 256) {
            int l = q / nn, r = q - l * nn;
            int i = r / n2, j = r - i * n2;
            float v;
            if (l == LYR - 1)
                v = l7[smap[i] * MAXNP + smap[j]];
            else
                v = g_sim[(size_t)(l * NCLS + cls) * MAXN * MAXN + smap[i] * MAXN + smap[j]];
            lsim[l * BLK + i * MAXNP + j] = v;
        }
        {
            uint32_t* mz = (uint32_t*)msk;
            for (int q = tid; q < LYR * BLK / 4; q += 256) mz[q] = 0u;
        }
        __syncthreads();

        // ---- phase 2: warp w = layer w knn (lane-per-row, R11 serial arithmetic) ----
        {
            const int l = w;
            const float* sm = lsim + l * BLK;
            unsigned char* mk = msk + l * BLK;
            for (int i = lane; i < n2; i += 32) {
                const float* row = sm + i * MAXNP;
                float rs = 0.f;
                int dg = 0, cand = 0;
                for (int j = 0; j < n2; j++) {
                    float v = row[j];
                    if (v > 0.f) { rs += v; dg++; if (j != i) cand++; }
                }
                float degf = (float)(dg > 0 ? dg : 1);
                float sc   = 1.0f / (1.0f + expf(-rs / degf));
                ema[l][i]   = 0.45f + 0.1f * sc;       // MOM*0.5 + (1-MOM)*score
                keepL[l][i] = (cand >= KTOP) ? 1 : 0;
            }
            __syncwarp();
            for (int i = lane; i < n2; i += 32) {
                if (!keepL[l][i]) continue;
                const float* row = sm + i * MAXNP;
                int ch[KTOP];
                top5_row(row, n2, i, ch);
#pragma unroll
                for (int t = 0; t < KTOP; t++) {
                    int j = ch[t];
                    if (j >= 0 && keepL[l][j]) mk[i * MAXNP + j] = 1;
                }
            }
        }
        __syncthreads();

        // ---- phase 3: warp t = layer pair t accumulation (from smem) ----
        if (w < NT) {
            const float*         sP = lsim + w * BLK;
            const float*         sC = lsim + (w + 1) * BLK;
            const unsigned char* mP = msk + w * BLK;
            const unsigned char* mC = msk + (w + 1) * BLK;
            float pnum = 0.f, pden = 0.f;
            for (int i = 0; i < n2; i++) {
                float ei = ema[w][i];
                for (int j = lane; j < n2; j += 32) {
                    if (i == j) continue;
                    int o  = i * MAXNP + j;
                    int ot = j * MAXNP + i;
                    int ml = mP[o] | mP[ot];          // symmetrized masks
                    int mc = mC[o] | mC[ot];
                    if (ml | mc) {
                        float wt = ei * ema[w][j];
                        float al = ml ? sP[o] : 0.f;  // A = sim * M (masked sims > 0)
                        float ac = mc ? sC[o] : 0.f;
                        float d  = ac - al;
                        pnum += d * d * wt;
                        pden += wt;
                    }
                }
            }
#pragma unroll
            for (int o = 16; o; o >>= 1) {
                pnum += __shfl_xor_sync(FULL, pnum, o);
                pden += __shfl_xor_sync(FULL, pden, o);
            }
            if (lane == 0) {
                g_pnum[w * NCLS + cls] = pnum;
                g_pden[w * NCLS + cls] = pden;
            }
        }
    } else {
        if (tid < NT) {
            g_pnum[tid * NCLS + cls] = 0.f;
            g_pden[tid * NCLS + cls] = 0.f;
        }
    }
    __threadfence();
    __syncthreads();
    if (tid == 0) {
        int old = atomicAdd(&g_ctr, 1);
        done = (old == NCLS - 1) ? 1 : 0;
    }
    __syncthreads();
    if (!done) return;

    // last block: deterministic combine of all 7*128 partials
    __shared__ float red[128];
    __shared__ float tnum[NT], tden[NT];
    for (int t2 = 0; t2 < NT; t2++) {
        if (tid < 128) red[tid] = g_pnum[t2 * NCLS + tid];
        __syncthreads();
        for (int s = 64; s; s >>= 1) { if (tid < s) red[tid] += red[tid + s]; __syncthreads(); }
        if (tid == 0) tnum[t2] = red[0];
        __syncthreads();
        if (tid < 128) red[tid] = g_pden[t2 * NCLS + tid];
        __syncthreads();
        for (int s = 64; s; s >>= 1) { if (tid < s) red[tid] += red[tid + s]; __syncthreads(); }
        if (tid == 0) tden[t2] = red[0];
        __syncthreads();
    }
    if (tid == 0) {
        float raw = 0.f;
        for (int t2 = 0; t2 < NT; t2++)
            if (tden[t2] > 0.f)                       // M_eff.sum() > 0 <=> any edge
                raw += tnum[t2] / fmaxf(tden[t2], 1e-8f);
        out[0] = 16.0f * (raw / 7.0f);                // LAMBDA_ALIGN_K * raw / (L-1)
        g_ctr = 0;                                    // reset for next graph replay
    }
}

extern "C" void kernel_launch(void* const* d_in, const int* in_sizes, int n_in,
                              void* d_out, int out_size) {
    const float* feats  = (const float*)d_in[0];
    const int*   labels = (const int*)d_in[1];   // int32 or int64; detected at runtime
    const int*   sids   = (const int*)d_in[2];
    float*       out    = (float*)d_out;

    const int DYN_SIMS = SCAP * DPAD * 16;                       // 41.3 KB
    const int DYN_MEGA = (LYR + 1) * BLK * 4 + LYR * BLK;        // 183,040 B
    cudaFuncSetAttribute(sims_kernel, cudaFuncAttributeMaxDynamicSharedMemorySize, DYN_SIMS);
    cudaFuncSetAttribute(mega_kernel, cudaFuncAttributeMaxDynamicSharedMemorySize, DYN_MEGA);

    members_kernel<<<NCLS, 256>>>(labels, sids);
    sims_kernel<<<LYR * NCLS, 256, DYN_SIMS>>>(feats);
    mega_kernel<<<NCLS, 256, DYN_MEGA>>>(out);
}